// round 1
// baseline (speedup 1.0000x reference)
#include <cuda_runtime.h>
#include <cuda_bf16.h>
#include <cstdint>

// Problem constants (fixed by the reference)
#define BATCH 4
#define TLEN  2048
#define CDIM  1024
#define MROWS (BATCH * TLEN)   // 8192
#define HALF  8
#define WTAPS 17               // 2*HALF + 1

// Scratch: __device__ globals (no allocation allowed in kernel_launch)
__device__ float g_q[MROWS * CDIM];
__device__ float g_k[MROWS * CDIM];
__device__ float g_v[MROWS * CDIM];
__device__ float g_ctx[MROWS * CDIM];

// ---------------------------------------------------------------------------
// SGEMM: C[m,n] = sum_k A[m,k] * Bw[n,k] + bias[n]
// A row-major [M,K]; Bw row-major [N,K] (i.e. computes A @ Bw^T + bias)
// Tile: 128x128x16, 256 threads, 8x8 per-thread microtile.
// M,N,K all divisible by tile dims (8192,1024,1024) — no bounds checks.
// ---------------------------------------------------------------------------
#define BM 128
#define BN 128
#define BK 16
#define TM 8
#define TN 8

__global__ __launch_bounds__(256, 2)
void sgemm_abt_bias(const float* __restrict__ A,
                    const float* __restrict__ Bw,
                    const float* __restrict__ bias,
                    float* __restrict__ Cout,
                    int M, int N, int K)
{
    __shared__ float As[BK][BM];   // transposed: As[k][m]
    __shared__ float Bs[BK][BN];   // transposed: Bs[k][n]

    const int tid  = threadIdx.x;
    const int bRow = blockIdx.y * BM;          // m origin
    const int bCol = blockIdx.x * BN;          // n origin
    const int tRow = (tid >> 4) * TM;          // 0..120
    const int tCol = (tid & 15) * TN;          // 0..120

    // Loader mapping: 256 threads, each loads 2x float4 along K per tile
    const int aRow = tid >> 2;                 // 0..63
    const int aCol = (tid & 3) * 4;            // 0,4,8,12

    const float* Aptr = A  + (size_t)bRow * K;
    const float* Bptr = Bw + (size_t)bCol * K;

    float acc[TM][TN];
    #pragma unroll
    for (int i = 0; i < TM; i++)
        #pragma unroll
        for (int j = 0; j < TN; j++) acc[i][j] = 0.0f;

    for (int k0 = 0; k0 < K; k0 += BK) {
        #pragma unroll
        for (int p = 0; p < 2; p++) {
            const int r = aRow + p * 64;
            float4 av = *(const float4*)(Aptr + (size_t)r * K + k0 + aCol);
            As[aCol + 0][r] = av.x;
            As[aCol + 1][r] = av.y;
            As[aCol + 2][r] = av.z;
            As[aCol + 3][r] = av.w;
            float4 bv = *(const float4*)(Bptr + (size_t)r * K + k0 + aCol);
            Bs[aCol + 0][r] = bv.x;
            Bs[aCol + 1][r] = bv.y;
            Bs[aCol + 2][r] = bv.z;
            Bs[aCol + 3][r] = bv.w;
        }
        __syncthreads();

        #pragma unroll
        for (int k = 0; k < BK; k++) {
            float regM[TM], regN[TN];
            // vectorized shared loads (rows are 128-float, 16B-aligned)
            float4 m0 = *(const float4*)&As[k][tRow];
            float4 m1 = *(const float4*)&As[k][tRow + 4];
            regM[0]=m0.x; regM[1]=m0.y; regM[2]=m0.z; regM[3]=m0.w;
            regM[4]=m1.x; regM[5]=m1.y; regM[6]=m1.z; regM[7]=m1.w;
            float4 n0 = *(const float4*)&Bs[k][tCol];
            float4 n1 = *(const float4*)&Bs[k][tCol + 4];
            regN[0]=n0.x; regN[1]=n0.y; regN[2]=n0.z; regN[3]=n0.w;
            regN[4]=n1.x; regN[5]=n1.y; regN[6]=n1.z; regN[7]=n1.w;
            #pragma unroll
            for (int i = 0; i < TM; i++)
                #pragma unroll
                for (int j = 0; j < TN; j++)
                    acc[i][j] = fmaf(regM[i], regN[j], acc[i][j]);
        }
        __syncthreads();
    }

    // Epilogue with bias, float4 stores
    #pragma unroll
    for (int i = 0; i < TM; i++) {
        const size_t row = (size_t)(bRow + tRow + i);
        float* crow = Cout + row * N + bCol + tCol;
        #pragma unroll
        for (int j = 0; j < TN; j += 4) {
            float4 o;
            o.x = acc[i][j + 0] + bias[bCol + tCol + j + 0];
            o.y = acc[i][j + 1] + bias[bCol + tCol + j + 1];
            o.z = acc[i][j + 2] + bias[bCol + tCol + j + 2];
            o.w = acc[i][j + 3] + bias[bCol + tCol + j + 3];
            *(float4*)(crow + j) = o;
        }
    }
}

// ---------------------------------------------------------------------------
// Local windowed attention, one CTA (128 threads) per token.
// scores[o] = q[t] . k[t+o-8] * scale  (invalid -> -inf), softmax, then
// ctx[t] = sum_o attn[o] * v[t+o-8]
// ---------------------------------------------------------------------------
__global__ __launch_bounds__(128)
void local_attn_kernel(const float* __restrict__ q,
                       const float* __restrict__ k,
                       const float* __restrict__ v,
                       float* __restrict__ ctx)
{
    const int bt   = blockIdx.x;            // 0..8191
    const int b    = bt >> 11;              // /2048
    const int t    = bt & 2047;
    const int tid  = threadIdx.x;
    const int lane = tid & 31;
    const int warp = tid >> 5;

    __shared__ float s_scores[WTAPS];
    __shared__ float s_attn[WTAPS];

    const float* qrow = q + (size_t)bt * CDIM;
    const size_t baseRow = (size_t)(b * TLEN) * CDIM;
    const float scale = 0.03125f;           // 1/sqrt(1024)

    // --- scores: 4 warps cover 17 taps ---
    for (int o = warp; o < WTAPS; o += 4) {
        const int j = t + o - HALF;
        if (j >= 0 && j < TLEN) {
            const float* krow = k + baseRow + (size_t)j * CDIM;
            float sum = 0.0f;
            #pragma unroll
            for (int c = lane * 4; c < CDIM; c += 32 * 4) {
                float4 qv = *(const float4*)(qrow + c);
                float4 kv = *(const float4*)(krow + c);
                sum += qv.x * kv.x + qv.y * kv.y + qv.z * kv.z + qv.w * kv.w;
            }
            #pragma unroll
            for (int off = 16; off > 0; off >>= 1)
                sum += __shfl_xor_sync(0xffffffffu, sum, off);
            if (lane == 0) s_scores[o] = sum * scale;
        } else {
            if (lane == 0) s_scores[o] = -3.4e38f;
        }
    }
    __syncthreads();

    // --- softmax over 17 taps (thread 0, trivially cheap) ---
    if (tid == 0) {
        float m = -3.4e38f;
        #pragma unroll
        for (int o = 0; o < WTAPS; o++) m = fmaxf(m, s_scores[o]);
        float e[WTAPS];
        float s = 0.0f;
        #pragma unroll
        for (int o = 0; o < WTAPS; o++) {
            float d = s_scores[o] - m;
            e[o] = (d < -80.0f) ? 0.0f : expf(d);
            s += e[o];
        }
        const float inv = 1.0f / s;
        #pragma unroll
        for (int o = 0; o < WTAPS; o++) s_attn[o] = e[o] * inv;
    }
    __syncthreads();

    // --- context: each thread owns 8 channels ---
    const int c0 = tid * 8;
    float4 acc0 = make_float4(0.f, 0.f, 0.f, 0.f);
    float4 acc1 = make_float4(0.f, 0.f, 0.f, 0.f);
    #pragma unroll
    for (int o = 0; o < WTAPS; o++) {
        const int j = t + o - HALF;
        if (j < 0 || j >= TLEN) continue;
        const float a = s_attn[o];
        const float* vrow = v + baseRow + (size_t)j * CDIM + c0;
        float4 v0 = *(const float4*)(vrow);
        float4 v1 = *(const float4*)(vrow + 4);
        acc0.x = fmaf(a, v0.x, acc0.x);
        acc0.y = fmaf(a, v0.y, acc0.y);
        acc0.z = fmaf(a, v0.z, acc0.z);
        acc0.w = fmaf(a, v0.w, acc0.w);
        acc1.x = fmaf(a, v1.x, acc1.x);
        acc1.y = fmaf(a, v1.y, acc1.y);
        acc1.z = fmaf(a, v1.z, acc1.z);
        acc1.w = fmaf(a, v1.w, acc1.w);
    }
    float* crow = ctx + (size_t)bt * CDIM + c0;
    *(float4*)(crow)     = acc0;
    *(float4*)(crow + 4) = acc1;
}

// ---------------------------------------------------------------------------
extern "C" void kernel_launch(void* const* d_in, const int* in_sizes, int n_in,
                              void* d_out, int out_size)
{
    const float* x  = (const float*)d_in[0];
    const float* Wq = (const float*)d_in[1];
    const float* bq = (const float*)d_in[2];
    const float* Wk = (const float*)d_in[3];
    const float* bk = (const float*)d_in[4];
    const float* Wv = (const float*)d_in[5];
    const float* bv = (const float*)d_in[6];
    const float* Wo = (const float*)d_in[7];
    const float* bo = (const float*)d_in[8];
    // d_in[9] = window (16), hardcoded above

    float *q, *k, *v, *ctx;
    cudaGetSymbolAddress((void**)&q,   g_q);
    cudaGetSymbolAddress((void**)&k,   g_k);
    cudaGetSymbolAddress((void**)&v,   g_v);
    cudaGetSymbolAddress((void**)&ctx, g_ctx);

    dim3 grid(CDIM / BN, MROWS / BM);   // (8, 64)
    dim3 block(256);

    sgemm_abt_bias<<<grid, block>>>(x,   Wq, bq, q,   MROWS, CDIM, CDIM);
    sgemm_abt_bias<<<grid, block>>>(x,   Wk, bk, k,   MROWS, CDIM, CDIM);
    sgemm_abt_bias<<<grid, block>>>(x,   Wv, bv, v,   MROWS, CDIM, CDIM);

    local_attn_kernel<<<MROWS, 128>>>(q, k, v, ctx);

    sgemm_abt_bias<<<grid, block>>>(ctx, Wo, bo, (float*)d_out, MROWS, CDIM, CDIM);
}

// round 4
// speedup vs baseline: 2.6664x; 2.6664x over previous
#include <cuda_runtime.h>
#include <cuda_bf16.h>
#include <cstdint>

// Problem constants (fixed by the reference)
#define BATCH 4
#define TLEN  2048
#define CDIM  1024
#define MROWS (BATCH * TLEN)   // 8192
#define HALF  8
#define WTAPS 17               // 2*HALF + 1

// Scratch: __device__ globals (no allocation allowed in kernel_launch)
__device__ float g_q[MROWS * CDIM];
__device__ float g_k[MROWS * CDIM];
__device__ float g_v[MROWS * CDIM];
__device__ float g_ctx[MROWS * CDIM];
__device__ float g_xr[MROWS * CDIM];     // tf32-rounded x
__device__ float g_wq[CDIM * CDIM];      // tf32-rounded weights
__device__ float g_wk[CDIM * CDIM];
__device__ float g_wv[CDIM * CDIM];
__device__ float g_wo[CDIM * CDIM];

// ---------------------------------------------------------------------------
// Round fp32 -> tf32 (rna) elementwise, float4 vectorized. May run in place.
// ---------------------------------------------------------------------------
__global__ __launch_bounds__(256)
void round_tf32_kernel(const float4* __restrict__ in, float4* __restrict__ out, int n4)
{
    int i = blockIdx.x * blockDim.x + threadIdx.x;
    if (i >= n4) return;
    float4 v = in[i];
    uint32_t a, b, c, d;
    asm("cvt.rna.tf32.f32 %0, %1;" : "=r"(a) : "f"(v.x));
    asm("cvt.rna.tf32.f32 %0, %1;" : "=r"(b) : "f"(v.y));
    asm("cvt.rna.tf32.f32 %0, %1;" : "=r"(c) : "f"(v.z));
    asm("cvt.rna.tf32.f32 %0, %1;" : "=r"(d) : "f"(v.w));
    float4 o;
    o.x = __uint_as_float(a); o.y = __uint_as_float(b);
    o.z = __uint_as_float(c); o.w = __uint_as_float(d);
    out[i] = o;
}

// ---------------------------------------------------------------------------
// TF32 tensor-core GEMM: C[m,n] = sum_k A[m,k]*Bw[n,k] + bias[n]
// A [M,K] row-major, Bw [N,K] row-major (A @ Bw^T). Inputs pre-rounded to tf32.
// Tile 128x128x16, 4 warps (64x64 each), cp.async double buffer.
// ---------------------------------------------------------------------------
#define BM 128
#define BN 128
#define BK 16
#define BKP 20   // padded row (floats): 20*4B=80B, 16B-aligned, conflict-free

__device__ __forceinline__ uint32_t smem_u32(const void* p) {
    return (uint32_t)__cvta_generic_to_shared(p);
}
__device__ __forceinline__ void cp_async16(uint32_t dst, const void* src) {
    asm volatile("cp.async.cg.shared.global [%0], [%1], 16;\n" :: "r"(dst), "l"(src));
}

__global__ __launch_bounds__(128)
void gemm_tf32_abt_bias(const float* __restrict__ A,
                        const float* __restrict__ Bw,
                        const float* __restrict__ bias,
                        float* __restrict__ Cout,
                        int M, int N, int K)
{
    __shared__ float As[2][BM][BKP];
    __shared__ float Bs[2][BM][BKP];

    const int tid  = threadIdx.x;
    const int lane = tid & 31;
    const int wid  = tid >> 5;
    const int wm   = wid >> 1;          // 0..1
    const int wn   = wid & 1;           // 0..1
    const int gid  = lane >> 2;         // 0..7
    const int tig  = lane & 3;          // 0..3

    const int bRow = blockIdx.y * BM;
    const int bCol = blockIdx.x * BN;

    const int ldRow = tid >> 2;         // 0..31
    const int ldCol = (tid & 3) << 2;   // 0,4,8,12

    const float* Ag = A  + (size_t)(bRow + ldRow) * K + ldCol;
    const float* Bg = Bw + (size_t)(bCol + ldRow) * K + ldCol;

    float acc[4][8][4];
    #pragma unroll
    for (int i = 0; i < 4; i++)
        #pragma unroll
        for (int j = 0; j < 8; j++)
            #pragma unroll
            for (int r = 0; r < 4; r++) acc[i][j][r] = 0.0f;

    auto issue = [&](int kt, int buf) {
        const int k0 = kt * BK;
        #pragma unroll
        for (int p = 0; p < 4; ++p) {
            cp_async16(smem_u32(&As[buf][ldRow + 32*p][ldCol]),
                       Ag + (size_t)(32*p) * K + k0);
            cp_async16(smem_u32(&Bs[buf][ldRow + 32*p][ldCol]),
                       Bg + (size_t)(32*p) * K + k0);
        }
        asm volatile("cp.async.commit_group;\n" ::);
    };

    issue(0, 0);
    const int KT = K / BK;
    for (int kt = 0; kt < KT; ++kt) {
        const int buf = kt & 1;
        if (kt + 1 < KT) {
            issue(kt + 1, buf ^ 1);
            asm volatile("cp.async.wait_group 1;\n" ::);
        } else {
            asm volatile("cp.async.wait_group 0;\n" ::);
        }
        __syncthreads();

        #pragma unroll
        for (int s = 0; s < 2; ++s) {
            const int kk = s * 8;
            uint32_t afr[4][4], bfr[8][2];
            #pragma unroll
            for (int i = 0; i < 4; ++i) {
                const int r = wm * 64 + 16 * i + gid;
                afr[i][0] = __float_as_uint(As[buf][r    ][kk + tig]);
                afr[i][1] = __float_as_uint(As[buf][r + 8][kk + tig]);
                afr[i][2] = __float_as_uint(As[buf][r    ][kk + tig + 4]);
                afr[i][3] = __float_as_uint(As[buf][r + 8][kk + tig + 4]);
            }
            #pragma unroll
            for (int j = 0; j < 8; ++j) {
                const int r = wn * 64 + 8 * j + gid;
                bfr[j][0] = __float_as_uint(Bs[buf][r][kk + tig]);
                bfr[j][1] = __float_as_uint(Bs[buf][r][kk + tig + 4]);
            }
            #pragma unroll
            for (int i = 0; i < 4; ++i)
                #pragma unroll
                for (int j = 0; j < 8; ++j) {
                    asm volatile(
                        "mma.sync.aligned.m16n8k8.row.col.f32.tf32.tf32.f32 "
                        "{%0,%1,%2,%3}, {%4,%5,%6,%7}, {%8,%9}, {%0,%1,%2,%3};\n"
                        : "+f"(acc[i][j][0]), "+f"(acc[i][j][1]),
                          "+f"(acc[i][j][2]), "+f"(acc[i][j][3])
                        : "r"(afr[i][0]), "r"(afr[i][1]),
                          "r"(afr[i][2]), "r"(afr[i][3]),
                          "r"(bfr[j][0]), "r"(bfr[j][1]));
                }
        }
        __syncthreads();
    }

    // Epilogue with bias
    #pragma unroll
    for (int i = 0; i < 4; ++i) {
        const int r0 = bRow + wm * 64 + 16 * i + gid;
        #pragma unroll
        for (int j = 0; j < 8; ++j) {
            const int c0 = bCol + wn * 64 + 8 * j + 2 * tig;
            const float b0 = bias[c0], b1 = bias[c0 + 1];
            float2 v0, v1;
            v0.x = acc[i][j][0] + b0; v0.y = acc[i][j][1] + b1;
            v1.x = acc[i][j][2] + b0; v1.y = acc[i][j][3] + b1;
            *(float2*)(Cout + (size_t)r0 * N + c0)       = v0;
            *(float2*)(Cout + (size_t)(r0 + 8) * N + c0) = v1;
        }
    }
}

// ---------------------------------------------------------------------------
// Local windowed attention, one CTA (128 threads) per token.
// ---------------------------------------------------------------------------
__global__ __launch_bounds__(128)
void local_attn_kernel(const float* __restrict__ q,
                       const float* __restrict__ k,
                       const float* __restrict__ v,
                       float* __restrict__ ctx)
{
    const int bt   = blockIdx.x;
    const int b    = bt >> 11;
    const int t    = bt & 2047;
    const int tid  = threadIdx.x;
    const int lane = tid & 31;
    const int warp = tid >> 5;

    __shared__ float s_scores[WTAPS];
    __shared__ float s_attn[WTAPS];

    const float* qrow = q + (size_t)bt * CDIM;
    const size_t baseRow = (size_t)(b * TLEN) * CDIM;
    const float scale = 0.03125f;

    for (int o = warp; o < WTAPS; o += 4) {
        const int j = t + o - HALF;
        if (j >= 0 && j < TLEN) {
            const float* krow = k + baseRow + (size_t)j * CDIM;
            float sum = 0.0f;
            #pragma unroll
            for (int c = lane * 4; c < CDIM; c += 32 * 4) {
                float4 qv = *(const float4*)(qrow + c);
                float4 kv = *(const float4*)(krow + c);
                sum += qv.x * kv.x + qv.y * kv.y + qv.z * kv.z + qv.w * kv.w;
            }
            #pragma unroll
            for (int off = 16; off > 0; off >>= 1)
                sum += __shfl_xor_sync(0xffffffffu, sum, off);
            if (lane == 0) s_scores[o] = sum * scale;
        } else {
            if (lane == 0) s_scores[o] = -3.4e38f;
        }
    }
    __syncthreads();

    if (tid == 0) {
        float m = -3.4e38f;
        #pragma unroll
        for (int o = 0; o < WTAPS; o++) m = fmaxf(m, s_scores[o]);
        float e[WTAPS];
        float s = 0.0f;
        #pragma unroll
        for (int o = 0; o < WTAPS; o++) {
            float d = s_scores[o] - m;
            e[o] = (d < -80.0f) ? 0.0f : expf(d);
            s += e[o];
        }
        const float inv = 1.0f / s;
        #pragma unroll
        for (int o = 0; o < WTAPS; o++) s_attn[o] = e[o] * inv;
    }
    __syncthreads();

    const int c0 = tid * 8;
    float4 acc0 = make_float4(0.f, 0.f, 0.f, 0.f);
    float4 acc1 = make_float4(0.f, 0.f, 0.f, 0.f);
    #pragma unroll
    for (int o = 0; o < WTAPS; o++) {
        const int j = t + o - HALF;
        if (j < 0 || j >= TLEN) continue;
        const float a = s_attn[o];
        const float* vrow = v + baseRow + (size_t)j * CDIM + c0;
        float4 v0 = *(const float4*)(vrow);
        float4 v1 = *(const float4*)(vrow + 4);
        acc0.x = fmaf(a, v0.x, acc0.x);
        acc0.y = fmaf(a, v0.y, acc0.y);
        acc0.z = fmaf(a, v0.z, acc0.z);
        acc0.w = fmaf(a, v0.w, acc0.w);
        acc1.x = fmaf(a, v1.x, acc1.x);
        acc1.y = fmaf(a, v1.y, acc1.y);
        acc1.z = fmaf(a, v1.z, acc1.z);
        acc1.w = fmaf(a, v1.w, acc1.w);
    }
    float* crow = ctx + (size_t)bt * CDIM + c0;
    *(float4*)(crow)     = acc0;
    *(float4*)(crow + 4) = acc1;
}

// ---------------------------------------------------------------------------
extern "C" void kernel_launch(void* const* d_in, const int* in_sizes, int n_in,
                              void* d_out, int out_size)
{
    const float* x  = (const float*)d_in[0];
    const float* Wq = (const float*)d_in[1];
    const float* bq = (const float*)d_in[2];
    const float* Wk = (const float*)d_in[3];
    const float* bk = (const float*)d_in[4];
    const float* Wv = (const float*)d_in[5];
    const float* bv = (const float*)d_in[6];
    const float* Wo = (const float*)d_in[7];
    const float* bo = (const float*)d_in[8];

    float *q, *k, *v, *ctx, *xr, *wq, *wk, *wv, *wo;
    cudaGetSymbolAddress((void**)&q,   g_q);
    cudaGetSymbolAddress((void**)&k,   g_k);
    cudaGetSymbolAddress((void**)&v,   g_v);
    cudaGetSymbolAddress((void**)&ctx, g_ctx);
    cudaGetSymbolAddress((void**)&xr,  g_xr);
    cudaGetSymbolAddress((void**)&wq,  g_wq);
    cudaGetSymbolAddress((void**)&wk,  g_wk);
    cudaGetSymbolAddress((void**)&wv,  g_wv);
    cudaGetSymbolAddress((void**)&wo,  g_wo);

    const int nx4 = MROWS * CDIM / 4;   // 2097152
    const int nw4 = CDIM * CDIM / 4;    // 262144

    // tf32 round (rna) all GEMM operands
    round_tf32_kernel<<<(nx4 + 255) / 256, 256>>>((const float4*)x,  (float4*)xr, nx4);
    round_tf32_kernel<<<(nw4 + 255) / 256, 256>>>((const float4*)Wq, (float4*)wq, nw4);
    round_tf32_kernel<<<(nw4 + 255) / 256, 256>>>((const float4*)Wk, (float4*)wk, nw4);
    round_tf32_kernel<<<(nw4 + 255) / 256, 256>>>((const float4*)Wv, (float4*)wv, nw4);
    round_tf32_kernel<<<(nw4 + 255) / 256, 256>>>((const float4*)Wo, (float4*)wo, nw4);

    dim3 grid(CDIM / BN, MROWS / BM);   // (8, 64)
    dim3 block(128);

    gemm_tf32_abt_bias<<<grid, block>>>(xr, wq, bq, q, MROWS, CDIM, CDIM);
    gemm_tf32_abt_bias<<<grid, block>>>(xr, wk, bk, k, MROWS, CDIM, CDIM);
    gemm_tf32_abt_bias<<<grid, block>>>(xr, wv, bv, v, MROWS, CDIM, CDIM);

    local_attn_kernel<<<MROWS, 128>>>(q, k, v, ctx);

    // round ctx in place (idempotent), then output projection
    round_tf32_kernel<<<(nx4 + 255) / 256, 256>>>((const float4*)ctx, (float4*)ctx, nx4);
    gemm_tf32_abt_bias<<<grid, block>>>(ctx, wo, bo, (float*)d_out, MROWS, CDIM, CDIM);
}

// round 5
// speedup vs baseline: 3.9564x; 1.4838x over previous
#include <cuda_runtime.h>
#include <cuda_bf16.h>
#include <cstdint>

// Problem constants (fixed by the reference)
#define BATCH 4
#define TLEN  2048
#define CDIM  1024
#define MROWS (BATCH * TLEN)   // 8192
#define HALF  8
#define WTAPS 17               // 2*HALF + 1

#define KT_BLOCKS (CDIM / 16)  // 64 k-blocks per packed row of blocks
#define BLK_FLOATS 2048        // 128x16 block

// Scratch: __device__ globals
__device__ float g_q[MROWS * CDIM];
__device__ float g_k[MROWS * CDIM];
__device__ float g_v[MROWS * CDIM];
__device__ float g_ctx[MROWS * CDIM];
__device__ float g_xa[MROWS * CDIM];     // packed+rounded activations (x, later ctx)
__device__ float g_wq[CDIM * CDIM];      // packed+rounded weights
__device__ float g_wk[CDIM * CDIM];
__device__ float g_wv[CDIM * CDIM];
__device__ float g_wo[CDIM * CDIM];

__device__ __forceinline__ uint32_t smem_u32(const void* p) {
    return (uint32_t)__cvta_generic_to_shared(p);
}
__device__ __forceinline__ void cp_async16(uint32_t dst, const void* src) {
    asm volatile("cp.async.cg.shared.global [%0], [%1], 16;\n" :: "r"(dst), "l"(src));
}
__device__ __forceinline__ float tf32_rna(float x) {
    uint32_t u;
    asm("cvt.rna.tf32.f32 %0, %1;" : "=r"(u) : "f"(x));
    return __uint_as_float(u);
}

// ---------------------------------------------------------------------------
// Pack A (activations): [M,K] fp32 -> tf32-rounded, fragment-major blocks.
// Block (mb,kb) at ((mb*KT + kb)*2048); inside:
//   offset = ((wm*2+s)*4 + i)*128 + lane*4 + reg
//   wm=m>>6, i=(m>>4)&3, gid=m&7, regm=(m>>3)&1 ; s=k>>3, tig=k&3, kbit=(k>>2)&1
//   lane = gid*4+tig, reg = regm | (kbit<<1)
// ---------------------------------------------------------------------------
__global__ __launch_bounds__(256)
void pack_a_kernel(const float* __restrict__ in, float* __restrict__ out, int M)
{
    const int idx = blockIdx.x * blockDim.x + threadIdx.x;   // one per float4
    const int total = M * (CDIM / 4);
    if (idx >= total) return;
    const int m  = idx / (CDIM / 4);
    const int k0 = (idx % (CDIM / 4)) * 4;

    float4 v = *(const float4*)(in + (size_t)m * CDIM + k0);
    float val[4] = { tf32_rna(v.x), tf32_rna(v.y), tf32_rna(v.z), tf32_rna(v.w) };

    const int mb = m >> 7, mloc = m & 127;
    const int wm = mloc >> 6, i = (mloc >> 4) & 3, gid = mloc & 7, regm = (mloc >> 3) & 1;
    const int kb = k0 >> 4, kloc = k0 & 15;
    const int s = kloc >> 3, kbit = (kloc >> 2) & 1;

    float* base = out + (size_t)(mb * KT_BLOCKS + kb) * BLK_FLOATS
                      + ((wm * 2 + s) * 4 + i) * 128 + regm + (kbit << 1);
    #pragma unroll
    for (int t = 0; t < 4; ++t)
        base[(gid * 4 + t) * 4] = val[t];   // lane = gid*4 + tig(t)
}

// ---------------------------------------------------------------------------
// Pack B (weights): [N,K] fp32 -> tf32-rounded, fragment-major blocks.
//   offset = (wn*8 + j)*128 + lane*4 + reg
//   wn=n>>6, j=(n>>3)&7, gid=n&7 ; s=k>>3, tig=k&3, kbit=(k>>2)&1
//   lane = gid*4+tig, reg = (s<<1) | kbit   (both k-steps packed per 16B)
// ---------------------------------------------------------------------------
__global__ __launch_bounds__(256)
void pack_b_kernel(const float* __restrict__ in, float* __restrict__ out)
{
    const int idx = blockIdx.x * blockDim.x + threadIdx.x;
    const int total = CDIM * (CDIM / 4);
    if (idx >= total) return;
    const int n  = idx / (CDIM / 4);
    const int k0 = (idx % (CDIM / 4)) * 4;

    float4 v = *(const float4*)(in + (size_t)n * CDIM + k0);
    float val[4] = { tf32_rna(v.x), tf32_rna(v.y), tf32_rna(v.z), tf32_rna(v.w) };

    const int nb = n >> 7, nloc = n & 127;
    const int wn = nloc >> 6, j = (nloc >> 3) & 7, gid = nloc & 7;
    const int kb = k0 >> 4, kloc = k0 & 15;
    const int s = kloc >> 3, kbit = (kloc >> 2) & 1;

    float* base = out + (size_t)(nb * KT_BLOCKS + kb) * BLK_FLOATS
                      + (wn * 8 + j) * 128 + (s << 1) + kbit;
    #pragma unroll
    for (int t = 0; t < 4; ++t)
        base[(gid * 4 + t) * 4] = val[t];
}

// ---------------------------------------------------------------------------
// TF32 GEMM on packed operands: C[m,n] = sum_k A[m,k]*B[n,k] + bias[n]
// 128x128x16 tile, 4 warps (64x64), 3-stage cp.async, LDS.128 fragment loads.
// ---------------------------------------------------------------------------
#define STAGES 3

__global__ __launch_bounds__(128)
void gemm_packed_tf32(const float* __restrict__ Ap,
                      const float* __restrict__ Bp,
                      const float* __restrict__ bias,
                      float* __restrict__ Cout,
                      int M, int N)
{
    __shared__ float As[STAGES][BLK_FLOATS];
    __shared__ float Bs[STAGES][BLK_FLOATS];

    const int tid  = threadIdx.x;
    const int lane = tid & 31;
    const int wid  = tid >> 5;
    const int wm   = wid >> 1;
    const int wn   = wid & 1;
    const int gid  = lane >> 2;
    const int tig  = lane & 3;

    const float* Ablk = Ap + (size_t)blockIdx.y * KT_BLOCKS * BLK_FLOATS;
    const float* Bblk = Bp + (size_t)blockIdx.x * KT_BLOCKS * BLK_FLOATS;

    float acc[4][8][4];
    #pragma unroll
    for (int i = 0; i < 4; i++)
        #pragma unroll
        for (int j = 0; j < 8; j++)
            #pragma unroll
            for (int r = 0; r < 4; r++) acc[i][j][r] = 0.0f;

    auto issue = [&](int stage, int kt) {
        const float* as = Ablk + (size_t)kt * BLK_FLOATS;
        const float* bs = Bblk + (size_t)kt * BLK_FLOATS;
        #pragma unroll
        for (int p = 0; p < 4; ++p) {
            const int off = (p * 128 + tid) * 4;
            cp_async16(smem_u32(&As[stage][off]), as + off);
            cp_async16(smem_u32(&Bs[stage][off]), bs + off);
        }
        asm volatile("cp.async.commit_group;\n" ::);
    };

    issue(0, 0);
    issue(1, 1);

    const int KT = KT_BLOCKS;   // 64
    for (int kt = 0; kt < KT; ++kt) {
        if (kt < KT - 1) asm volatile("cp.async.wait_group 1;\n" ::);
        else             asm volatile("cp.async.wait_group 0;\n" ::);
        __syncthreads();
        if (kt + 2 < KT) issue((kt + 2) % STAGES, kt + 2);

        const int stage = kt % STAGES;

        // B fragments: 8 x LDS.128, each covers both k-steps (regs: s0b0,s0b1,s1b0,s1b1)
        uint4 bfr[8];
        #pragma unroll
        for (int j = 0; j < 8; ++j)
            bfr[j] = *(const uint4*)&Bs[stage][(wn * 8 + j) * 128 + lane * 4];

        #pragma unroll
        for (int s = 0; s < 2; ++s) {
            uint4 afr[4];
            #pragma unroll
            for (int i = 0; i < 4; ++i)
                afr[i] = *(const uint4*)&As[stage][((wm * 2 + s) * 4 + i) * 128 + lane * 4];

            #pragma unroll
            for (int i = 0; i < 4; ++i)
                #pragma unroll
                for (int j = 0; j < 8; ++j) {
                    uint32_t b0 = s ? bfr[j].z : bfr[j].x;
                    uint32_t b1 = s ? bfr[j].w : bfr[j].y;
                    asm volatile(
                        "mma.sync.aligned.m16n8k8.row.col.f32.tf32.tf32.f32 "
                        "{%0,%1,%2,%3}, {%4,%5,%6,%7}, {%8,%9}, {%0,%1,%2,%3};\n"
                        : "+f"(acc[i][j][0]), "+f"(acc[i][j][1]),
                          "+f"(acc[i][j][2]), "+f"(acc[i][j][3])
                        : "r"(afr[i].x), "r"(afr[i].y), "r"(afr[i].z), "r"(afr[i].w),
                          "r"(b0), "r"(b1));
                }
        }
    }
    __syncthreads();

    // Epilogue with bias
    const int bRow = blockIdx.y * 128;
    const int bCol = blockIdx.x * 128;
    #pragma unroll
    for (int i = 0; i < 4; ++i) {
        const int r0 = bRow + wm * 64 + 16 * i + gid;
        #pragma unroll
        for (int j = 0; j < 8; ++j) {
            const int c0 = bCol + wn * 64 + 8 * j + 2 * tig;
            const float b0 = bias[c0], b1 = bias[c0 + 1];
            float2 v0, v1;
            v0.x = acc[i][j][0] + b0; v0.y = acc[i][j][1] + b1;
            v1.x = acc[i][j][2] + b0; v1.y = acc[i][j][3] + b1;
            *(float2*)(Cout + (size_t)r0 * N + c0)       = v0;
            *(float2*)(Cout + (size_t)(r0 + 8) * N + c0) = v1;
        }
    }
}

// ---------------------------------------------------------------------------
// Local windowed attention, one CTA (128 threads) per token.
// ---------------------------------------------------------------------------
__global__ __launch_bounds__(128)
void local_attn_kernel(const float* __restrict__ q,
                       const float* __restrict__ k,
                       const float* __restrict__ v,
                       float* __restrict__ ctx)
{
    const int bt   = blockIdx.x;
    const int b    = bt >> 11;
    const int t    = bt & 2047;
    const int tid  = threadIdx.x;
    const int lane = tid & 31;
    const int warp = tid >> 5;

    __shared__ float s_scores[WTAPS];
    __shared__ float s_attn[WTAPS];

    const float* qrow = q + (size_t)bt * CDIM;
    const size_t baseRow = (size_t)(b * TLEN) * CDIM;
    const float scale = 0.03125f;

    for (int o = warp; o < WTAPS; o += 4) {
        const int j = t + o - HALF;
        if (j >= 0 && j < TLEN) {
            const float* krow = k + baseRow + (size_t)j * CDIM;
            float sum = 0.0f;
            #pragma unroll
            for (int c = lane * 4; c < CDIM; c += 32 * 4) {
                float4 qv = *(const float4*)(qrow + c);
                float4 kv = *(const float4*)(krow + c);
                sum += qv.x * kv.x + qv.y * kv.y + qv.z * kv.z + qv.w * kv.w;
            }
            #pragma unroll
            for (int off = 16; off > 0; off >>= 1)
                sum += __shfl_xor_sync(0xffffffffu, sum, off);
            if (lane == 0) s_scores[o] = sum * scale;
        } else {
            if (lane == 0) s_scores[o] = -3.4e38f;
        }
    }
    __syncthreads();

    if (tid == 0) {
        float m = -3.4e38f;
        #pragma unroll
        for (int o = 0; o < WTAPS; o++) m = fmaxf(m, s_scores[o]);
        float e[WTAPS];
        float s = 0.0f;
        #pragma unroll
        for (int o = 0; o < WTAPS; o++) {
            float d = s_scores[o] - m;
            e[o] = (d < -80.0f) ? 0.0f : expf(d);
            s += e[o];
        }
        const float inv = 1.0f / s;
        #pragma unroll
        for (int o = 0; o < WTAPS; o++) s_attn[o] = e[o] * inv;
    }
    __syncthreads();

    const int c0 = tid * 8;
    float4 acc0 = make_float4(0.f, 0.f, 0.f, 0.f);
    float4 acc1 = make_float4(0.f, 0.f, 0.f, 0.f);
    #pragma unroll
    for (int o = 0; o < WTAPS; o++) {
        const int j = t + o - HALF;
        if (j < 0 || j >= TLEN) continue;
        const float a = s_attn[o];
        const float* vrow = v + baseRow + (size_t)j * CDIM + c0;
        float4 v0 = *(const float4*)(vrow);
        float4 v1 = *(const float4*)(vrow + 4);
        acc0.x = fmaf(a, v0.x, acc0.x);
        acc0.y = fmaf(a, v0.y, acc0.y);
        acc0.z = fmaf(a, v0.z, acc0.z);
        acc0.w = fmaf(a, v0.w, acc0.w);
        acc1.x = fmaf(a, v1.x, acc1.x);
        acc1.y = fmaf(a, v1.y, acc1.y);
        acc1.z = fmaf(a, v1.z, acc1.z);
        acc1.w = fmaf(a, v1.w, acc1.w);
    }
    float* crow = ctx + (size_t)bt * CDIM + c0;
    *(float4*)(crow)     = acc0;
    *(float4*)(crow + 4) = acc1;
}

// ---------------------------------------------------------------------------
extern "C" void kernel_launch(void* const* d_in, const int* in_sizes, int n_in,
                              void* d_out, int out_size)
{
    const float* x  = (const float*)d_in[0];
    const float* Wq = (const float*)d_in[1];
    const float* bq = (const float*)d_in[2];
    const float* Wk = (const float*)d_in[3];
    const float* bk = (const float*)d_in[4];
    const float* Wv = (const float*)d_in[5];
    const float* bv = (const float*)d_in[6];
    const float* Wo = (const float*)d_in[7];
    const float* bo = (const float*)d_in[8];

    float *q, *k, *v, *ctx, *xa, *wq, *wk, *wv, *wo;
    cudaGetSymbolAddress((void**)&q,   g_q);
    cudaGetSymbolAddress((void**)&k,   g_k);
    cudaGetSymbolAddress((void**)&v,   g_v);
    cudaGetSymbolAddress((void**)&ctx, g_ctx);
    cudaGetSymbolAddress((void**)&xa,  g_xa);
    cudaGetSymbolAddress((void**)&wq,  g_wq);
    cudaGetSymbolAddress((void**)&wk,  g_wk);
    cudaGetSymbolAddress((void**)&wv,  g_wv);
    cudaGetSymbolAddress((void**)&wo,  g_wo);

    const int na = MROWS * CDIM / 4;   // activation float4 count
    const int nb = CDIM * CDIM / 4;    // weight float4 count

    pack_a_kernel<<<(na + 255) / 256, 256>>>(x,  xa, MROWS);
    pack_b_kernel<<<(nb + 255) / 256, 256>>>(Wq, wq);
    pack_b_kernel<<<(nb + 255) / 256, 256>>>(Wk, wk);
    pack_b_kernel<<<(nb + 255) / 256, 256>>>(Wv, wv);
    pack_b_kernel<<<(nb + 255) / 256, 256>>>(Wo, wo);

    dim3 grid(CDIM / 128, MROWS / 128);   // (8, 64)
    dim3 block(128);

    gemm_packed_tf32<<<grid, block>>>(xa, wq, bq, q, MROWS, CDIM);
    gemm_packed_tf32<<<grid, block>>>(xa, wk, bk, k, MROWS, CDIM);
    gemm_packed_tf32<<<grid, block>>>(xa, wv, bv, v, MROWS, CDIM);

    local_attn_kernel<<<MROWS, 128>>>(q, k, v, ctx);

    // repack ctx (x no longer needed — reuse xa), then output projection
    pack_a_kernel<<<(na + 255) / 256, 256>>>(ctx, xa, MROWS);
    gemm_packed_tf32<<<grid, block>>>(xa, wo, bo, (float*)d_out, MROWS, CDIM);
}

// round 8
// speedup vs baseline: 4.0774x; 1.0306x over previous
#include <cuda_runtime.h>
#include <cuda_bf16.h>
#include <cstdint>

// Problem constants (fixed by the reference)
#define BATCH 4
#define TLEN  2048
#define CDIM  1024
#define MROWS (BATCH * TLEN)   // 8192
#define HALF  8
#define WTAPS 17               // 2*HALF + 1

#define KT_BLOCKS (CDIM / 16)  // 64 k-blocks per packed row of blocks
#define BLK_FLOATS 2048        // 128x16 block

// Scratch: __device__ globals
__device__ float g_q[MROWS * CDIM];
__device__ float g_k[MROWS * CDIM];
__device__ float g_v[MROWS * CDIM];
__device__ float g_xa[MROWS * CDIM];     // packed+rounded activations (x, later ctx)
__device__ float g_wq[CDIM * CDIM];      // packed+rounded weights
__device__ float g_wk[CDIM * CDIM];
__device__ float g_wv[CDIM * CDIM];
__device__ float g_wo[CDIM * CDIM];

__device__ __forceinline__ uint32_t smem_u32(const void* p) {
    return (uint32_t)__cvta_generic_to_shared(p);
}
__device__ __forceinline__ void cp_async16(uint32_t dst, const void* src) {
    asm volatile("cp.async.cg.shared.global [%0], [%1], 16;\n" :: "r"(dst), "l"(src));
}
__device__ __forceinline__ float tf32_rna(float x) {
    uint32_t u;
    asm("cvt.rna.tf32.f32 %0, %1;" : "=r"(u) : "f"(x));
    return __uint_as_float(u);
}

// ---------------------------------------------------------------------------
// Pack A (activations) v2: [M,K] fp32 -> tf32-rounded, fragment-major blocks.
// One 16B output chunk per thread (coalesced ST.128).
// Block (mb,kb) at ((mb*KT+kb)*2048); float index inside block:
//   ((wm*2+s)*4 + i)*128 + lane*4 + r,  lane=gid*4+tig, r=regm|(kbit<<1)
//   m = mb*128 + wm*64 + i*16 + regm*8 + gid ; k = kb*16 + s*8 + kbit*4 + tig
// ---------------------------------------------------------------------------
__global__ __launch_bounds__(256)
void pack_a_kernel(const float* __restrict__ in, float* __restrict__ out, int M)
{
    const int idx = blockIdx.x * blockDim.x + threadIdx.x;   // one 16B chunk
    const int total = M * (CDIM / 4);
    if (idx >= total) return;

    const int cid = idx & 511;          // chunk within 128x16 block
    const int blk = idx >> 9;
    const int mb  = blk >> 6;           // / KT_BLOCKS
    const int kb  = blk & 63;

    const int lane = cid & 31;
    const int grp  = cid >> 5;          // 0..15
    const int i    = grp & 3;
    const int s    = (grp >> 2) & 1;
    const int wm   = grp >> 3;
    const int gid  = lane >> 2;
    const int tig  = lane & 3;

    const int m0 = mb * 128 + wm * 64 + i * 16 + gid;   // + regm*8
    const int k0 = kb * 16 + s * 8 + tig;               // + kbit*4

    float4 o;
    o.x = tf32_rna(in[(size_t)(m0    ) * CDIM + k0    ]);   // r=0: regm=0,kbit=0
    o.y = tf32_rna(in[(size_t)(m0 + 8) * CDIM + k0    ]);   // r=1: regm=1,kbit=0
    o.z = tf32_rna(in[(size_t)(m0    ) * CDIM + k0 + 4]);   // r=2: regm=0,kbit=1
    o.w = tf32_rna(in[(size_t)(m0 + 8) * CDIM + k0 + 4]);   // r=3: regm=1,kbit=1
    *(float4*)(out + (size_t)idx * 4) = o;
}

// ---------------------------------------------------------------------------
// Pack B (weights): [N,K] fp32 -> tf32-rounded, fragment-major blocks.
// ---------------------------------------------------------------------------
__global__ __launch_bounds__(256)
void pack_b_kernel(const float* __restrict__ in, float* __restrict__ out)
{
    const int idx = blockIdx.x * blockDim.x + threadIdx.x;
    const int total = CDIM * (CDIM / 4);
    if (idx >= total) return;
    const int n  = idx / (CDIM / 4);
    const int k0 = (idx % (CDIM / 4)) * 4;

    float4 v = *(const float4*)(in + (size_t)n * CDIM + k0);
    float val[4] = { tf32_rna(v.x), tf32_rna(v.y), tf32_rna(v.z), tf32_rna(v.w) };

    const int nb = n >> 7, nloc = n & 127;
    const int wn = nloc >> 6, j = (nloc >> 3) & 7, gid = nloc & 7;
    const int kb = k0 >> 4, kloc = k0 & 15;
    const int s = kloc >> 3, kbit = (kloc >> 2) & 1;

    float* base = out + (size_t)(nb * KT_BLOCKS + kb) * BLK_FLOATS
                      + (wn * 8 + j) * 128 + (s << 1) + kbit;
    #pragma unroll
    for (int t = 0; t < 4; ++t)
        base[(gid * 4 + t) * 4] = val[t];
}

// ---------------------------------------------------------------------------
// TF32 GEMM on packed operands: C[m,n] = sum_k A[m,k]*B[n,k] + bias[n]
// 128x128x16 tile, 4 warps (64x64), 3-stage cp.async, LDS.128 fragment loads.
// blockIdx.z selects (B, bias, C) triple -> fused QKV in one launch.
// ---------------------------------------------------------------------------
#define STAGES 3

__global__ __launch_bounds__(128)
void gemm_packed_tf32(const float* __restrict__ Ap,
                      const float* __restrict__ B0, const float* __restrict__ B1,
                      const float* __restrict__ B2,
                      const float* __restrict__ bias0, const float* __restrict__ bias1,
                      const float* __restrict__ bias2,
                      float* __restrict__ C0, float* __restrict__ C1,
                      float* __restrict__ C2,
                      int M, int N)
{
    __shared__ float As[STAGES][BLK_FLOATS];
    __shared__ float Bs[STAGES][BLK_FLOATS];

    const int z = blockIdx.z;
    const float* Bp   = (z == 0) ? B0   : (z == 1) ? B1   : B2;
    const float* bias = (z == 0) ? bias0 : (z == 1) ? bias1 : bias2;
    float*       Cout = (z == 0) ? C0   : (z == 1) ? C1   : C2;

    const int tid  = threadIdx.x;
    const int lane = tid & 31;
    const int wid  = tid >> 5;
    const int wm   = wid >> 1;
    const int wn   = wid & 1;
    const int gid  = lane >> 2;
    const int tig  = lane & 3;

    const float* Ablk = Ap + (size_t)blockIdx.y * KT_BLOCKS * BLK_FLOATS;
    const float* Bblk = Bp + (size_t)blockIdx.x * KT_BLOCKS * BLK_FLOATS;

    float acc[4][8][4];
    #pragma unroll
    for (int i = 0; i < 4; i++)
        #pragma unroll
        for (int j = 0; j < 8; j++)
            #pragma unroll
            for (int r = 0; r < 4; r++) acc[i][j][r] = 0.0f;

    auto issue = [&](int stage, int kt) {
        const float* as = Ablk + (size_t)kt * BLK_FLOATS;
        const float* bs = Bblk + (size_t)kt * BLK_FLOATS;
        #pragma unroll
        for (int p = 0; p < 4; ++p) {
            const int off = (p * 128 + tid) * 4;
            cp_async16(smem_u32(&As[stage][off]), as + off);
            cp_async16(smem_u32(&Bs[stage][off]), bs + off);
        }
        asm volatile("cp.async.commit_group;\n" ::);
    };

    issue(0, 0);
    issue(1, 1);

    const int KT = KT_BLOCKS;   // 64
    for (int kt = 0; kt < KT; ++kt) {
        if (kt < KT - 1) asm volatile("cp.async.wait_group 1;\n" ::);
        else             asm volatile("cp.async.wait_group 0;\n" ::);
        __syncthreads();
        if (kt + 2 < KT) issue((kt + 2) % STAGES, kt + 2);

        const int stage = kt % STAGES;

        uint4 bfr[8];
        #pragma unroll
        for (int j = 0; j < 8; ++j)
            bfr[j] = *(const uint4*)&Bs[stage][(wn * 8 + j) * 128 + lane * 4];

        #pragma unroll
        for (int s = 0; s < 2; ++s) {
            uint4 afr[4];
            #pragma unroll
            for (int i = 0; i < 4; ++i)
                afr[i] = *(const uint4*)&As[stage][((wm * 2 + s) * 4 + i) * 128 + lane * 4];

            #pragma unroll
            for (int i = 0; i < 4; ++i)
                #pragma unroll
                for (int j = 0; j < 8; ++j) {
                    uint32_t b0 = s ? bfr[j].z : bfr[j].x;
                    uint32_t b1 = s ? bfr[j].w : bfr[j].y;
                    asm volatile(
                        "mma.sync.aligned.m16n8k8.row.col.f32.tf32.tf32.f32 "
                        "{%0,%1,%2,%3}, {%4,%5,%6,%7}, {%8,%9}, {%0,%1,%2,%3};\n"
                        : "+f"(acc[i][j][0]), "+f"(acc[i][j][1]),
                          "+f"(acc[i][j][2]), "+f"(acc[i][j][3])
                        : "r"(afr[i].x), "r"(afr[i].y), "r"(afr[i].z), "r"(afr[i].w),
                          "r"(b0), "r"(b1));
                }
        }
    }
    __syncthreads();

    // Epilogue with bias
    const int bRow = blockIdx.y * 128;
    const int bCol = blockIdx.x * 128;
    #pragma unroll
    for (int i = 0; i < 4; ++i) {
        const int r0 = bRow + wm * 64 + 16 * i + gid;
        #pragma unroll
        for (int j = 0; j < 8; ++j) {
            const int c0 = bCol + wn * 64 + 8 * j + 2 * tig;
            const float b0 = bias[c0], b1 = bias[c0 + 1];
            float2 v0, v1;
            v0.x = acc[i][j][0] + b0; v0.y = acc[i][j][1] + b1;
            v1.x = acc[i][j][2] + b0; v1.y = acc[i][j][3] + b1;
            *(float2*)(Cout + (size_t)r0 * N + c0)       = v0;
            *(float2*)(Cout + (size_t)(r0 + 8) * N + c0) = v1;
        }
    }
}

// ---------------------------------------------------------------------------
// Local windowed attention, one CTA (128 threads) per token.
// Writes ctx directly in packed-A fragment layout (tf32-rounded) -> feeds
// the output-projection GEMM with no intermediate pack pass.
// ---------------------------------------------------------------------------
__global__ __launch_bounds__(128)
void local_attn_kernel(const float* __restrict__ q,
                       const float* __restrict__ k,
                       const float* __restrict__ v,
                       float* __restrict__ ctx_packed)
{
    const int bt   = blockIdx.x;
    const int b    = bt >> 11;
    const int t    = bt & 2047;
    const int tid  = threadIdx.x;
    const int lane = tid & 31;
    const int warp = tid >> 5;

    __shared__ float s_scores[WTAPS];
    __shared__ float s_attn[32];

    const float* qrow = q + (size_t)bt * CDIM;
    const size_t baseRow = (size_t)(b * TLEN) * CDIM;
    const float scale = 0.03125f;

    // --- scores: 4 warps cover 17 taps ---
    for (int o = warp; o < WTAPS; o += 4) {
        const int j = t + o - HALF;
        if (j >= 0 && j < TLEN) {
            const float* krow = k + baseRow + (size_t)j * CDIM;
            float sum = 0.0f;
            #pragma unroll
            for (int c = lane * 4; c < CDIM; c += 32 * 4) {
                float4 qv = *(const float4*)(qrow + c);
                float4 kv = *(const float4*)(krow + c);
                sum += qv.x * kv.x + qv.y * kv.y + qv.z * kv.z + qv.w * kv.w;
            }
            #pragma unroll
            for (int off = 16; off > 0; off >>= 1)
                sum += __shfl_xor_sync(0xffffffffu, sum, off);
            if (lane == 0) s_scores[o] = sum * scale;
        } else {
            if (lane == 0) s_scores[o] = -3.4e38f;
        }
    }
    __syncthreads();

    // --- softmax: warp 0, one tap per lane ---
    if (warp == 0) {
        float sc = (lane < WTAPS) ? s_scores[lane] : -3.4e38f;
        float m = sc;
        #pragma unroll
        for (int off = 16; off > 0; off >>= 1)
            m = fmaxf(m, __shfl_xor_sync(0xffffffffu, m, off));
        float e = (lane < WTAPS) ? __expf(sc - m) : 0.0f;
        float ssum = e;
        #pragma unroll
        for (int off = 16; off > 0; off >>= 1)
            ssum += __shfl_xor_sync(0xffffffffu, ssum, off);
        s_attn[lane] = e * (1.0f / ssum);   // lanes >=17 write 0 (harmless)
    }
    __syncthreads();

    // --- context: each thread owns 8 channels ---
    const int c0 = tid * 8;
    float4 acc0 = make_float4(0.f, 0.f, 0.f, 0.f);
    float4 acc1 = make_float4(0.f, 0.f, 0.f, 0.f);
    #pragma unroll
    for (int o = 0; o < WTAPS; o++) {
        const int j = t + o - HALF;
        if (j < 0 || j >= TLEN) continue;
        const float a = s_attn[o];
        const float* vrow = v + baseRow + (size_t)j * CDIM + c0;
        float4 v0 = *(const float4*)(vrow);
        float4 v1 = *(const float4*)(vrow + 4);
        acc0.x = fmaf(a, v0.x, acc0.x);
        acc0.y = fmaf(a, v0.y, acc0.y);
        acc0.z = fmaf(a, v0.z, acc0.z);
        acc0.w = fmaf(a, v0.w, acc0.w);
        acc1.x = fmaf(a, v1.x, acc1.x);
        acc1.y = fmaf(a, v1.y, acc1.y);
        acc1.z = fmaf(a, v1.z, acc1.z);
        acc1.w = fmaf(a, v1.w, acc1.w);
    }

    // --- packed-layout store (m = bt, k = c0..c0+7), tf32-rounded ---
    const int mb = bt >> 7, mloc = bt & 127;
    const int wm = mloc >> 6, fi = (mloc >> 4) & 3, regm = (mloc >> 3) & 1, gid = mloc & 7;
    const int kb = c0 >> 4, sbit = (c0 >> 3) & 1;
    float* base = ctx_packed + (size_t)(mb * KT_BLOCKS + kb) * BLK_FLOATS
                             + ((wm * 2 + sbit) * 4 + fi) * 128 + regm;
    float vals[8] = { acc0.x, acc0.y, acc0.z, acc0.w, acc1.x, acc1.y, acc1.z, acc1.w };
    #pragma unroll
    for (int tt = 0; tt < 8; ++tt) {
        // k = c0+tt: kbit=tt>>2, tig=tt&3 ; float index = (gid*4+tig)*4 + 2*kbit
        base[(gid * 4 + (tt & 3)) * 4 + ((tt >> 2) << 1)] = tf32_rna(vals[tt]);
    }
}

// ---------------------------------------------------------------------------
extern "C" void kernel_launch(void* const* d_in, const int* in_sizes, int n_in,
                              void* d_out, int out_size)
{
    const float* x  = (const float*)d_in[0];
    const float* Wq = (const float*)d_in[1];
    const float* bq = (const float*)d_in[2];
    const float* Wk = (const float*)d_in[3];
    const float* bk = (const float*)d_in[4];
    const float* Wv = (const float*)d_in[5];
    const float* bv = (const float*)d_in[6];
    const float* Wo = (const float*)d_in[7];
    const float* bo = (const float*)d_in[8];

    float *q, *k, *v, *xa, *wq, *wk, *wv, *wo;
    cudaGetSymbolAddress((void**)&q,  g_q);
    cudaGetSymbolAddress((void**)&k,  g_k);
    cudaGetSymbolAddress((void**)&v,  g_v);
    cudaGetSymbolAddress((void**)&xa, g_xa);
    cudaGetSymbolAddress((void**)&wq, g_wq);
    cudaGetSymbolAddress((void**)&wk, g_wk);
    cudaGetSymbolAddress((void**)&wv, g_wv);
    cudaGetSymbolAddress((void**)&wo, g_wo);

    const int na = MROWS * CDIM / 4;   // 16B chunks in activations
    const int nb = CDIM * CDIM / 4;    // float4 count in weights

    pack_a_kernel<<<(na + 255) / 256, 256>>>(x,  xa, MROWS);
    pack_b_kernel<<<(nb + 255) / 256, 256>>>(Wq, wq);
    pack_b_kernel<<<(nb + 255) / 256, 256>>>(Wk, wk);
    pack_b_kernel<<<(nb + 255) / 256, 256>>>(Wv, wv);
    pack_b_kernel<<<(nb + 255) / 256, 256>>>(Wo, wo);

    dim3 block(128);

    // Fused Q/K/V projection: one launch, z selects weight/bias/output
    dim3 grid_qkv(CDIM / 128, MROWS / 128, 3);   // (8, 64, 3)
    gemm_packed_tf32<<<grid_qkv, block>>>(xa, wq, wk, wv, bq, bk, bv,
                                          q, k, v, MROWS, CDIM);

    // Attention: writes packed+rounded ctx straight into xa
    local_attn_kernel<<<MROWS, 128>>>(q, k, v, xa);

    // Output projection
    dim3 grid_o(CDIM / 128, MROWS / 128, 1);
    gemm_packed_tf32<<<grid_o, block>>>(xa, wo, wo, wo, bo, bo, bo,
                                        (float*)d_out, (float*)d_out, (float*)d_out,
                                        MROWS, CDIM);
}